// round 1
// baseline (speedup 1.0000x reference)
#include <cuda_runtime.h>

#define Bb  256
#define Tt  256
#define Cc  384
#define Hh  6
#define HSs 64
#define Pp  307
#define BT  (Bb*Tt)            // 65536 tokens
#define C3  (3*Cc)             // 1152
#define NS_ITERS 40

// ---------------- scratch (device globals; no allocation at runtime) ----------------
__device__ float g_h1  [(size_t)BT*Cc];   // ln1 output
__device__ float g_qkv [(size_t)BT*C3];   // packed q|k|v per token
__device__ float g_attn[(size_t)BT*Cc];
__device__ float g_h2  [(size_t)BT*Cc];   // proj + residual
__device__ float g_h3  [(size_t)BT*Cc];   // ln2 output
__device__ float g_h4  [(size_t)BT*Cc];   // h3 @ O_in
__device__ float g_ff  [(size_t)BT*Pp];   // relu(h4 @ W1 + b1)
__device__ float g_h6  [(size_t)BT*Cc];   // ff @ W2 + b2
__device__ float g_X0  [2*Cc*Cc];         // Newton-Schulz ping
__device__ float g_X1  [2*Cc*Cc];         // Newton-Schulz pong
__device__ float g_Tm  [2*Cc*Cc];         // X*X^T scratch
__device__ float g_Wqkv[Cc*C3];           // packed qkv weights [C, 3C]
__device__ float g_sc  [2];               // 1/frobenius norms

// ---------------- generic tiled fp32 GEMM ----------------
// C = alpha * A@B (+ bias) (+ beta*Res), optional relu. B optionally transposed (B is [N,K]).
// Batched via blockIdx.z with element strides sA,sB,sC (Res shares sC).
template<bool TB, bool RELU, bool BIAS, bool RES>
__global__ __launch_bounds__(256)
void gemm_k(const float* __restrict__ A, const float* __restrict__ Bm,
            const float* __restrict__ bias, const float* __restrict__ Res,
            float* __restrict__ Cm, int M, int N, int K,
            float alpha, float beta, long sA, long sB, long sC)
{
    const int BM = 64, BN = 64, BK = 16;
    __shared__ float As[BK][BM + 1];
    __shared__ float Bs[BK][BN + 1];
    long bz = blockIdx.z;
    A  += bz * sA;  Bm += bz * sB;  Cm += bz * sC;
    const float* Rp = RES ? Res + bz * sC : nullptr;

    int m0 = blockIdx.y * BM, n0 = blockIdx.x * BN;
    int tid = threadIdx.x;
    int ty = tid >> 4, tx = tid & 15;

    float acc[4][4] = {};
    for (int k0 = 0; k0 < K; k0 += BK) {
        #pragma unroll
        for (int i = 0; i < 4; i++) {                 // A tile 64x16
            int idx = tid + i * 256;
            int m = idx >> 4, k = idx & 15;
            int gm = m0 + m, gk = k0 + k;
            float va = 0.f;
            if (gm < M && gk < K) va = A[(long)gm * K + gk];
            As[k][m] = va;
        }
        #pragma unroll
        for (int i = 0; i < 4; i++) {                 // B tile 16x64
            int idx = tid + i * 256;
            int k = idx >> 6, n = idx & 63;
            int gk = k0 + k, gn = n0 + n;
            float vb = 0.f;
            if (TB) { if (gn < N && gk < K) vb = Bm[(long)gn * K + gk]; }
            else    { if (gk < K && gn < N) vb = Bm[(long)gk * N + gn]; }
            Bs[k][n] = vb;
        }
        __syncthreads();
        #pragma unroll
        for (int k = 0; k < BK; k++) {
            float a[4], b[4];
            #pragma unroll
            for (int i = 0; i < 4; i++) a[i] = As[k][ty * 4 + i];
            #pragma unroll
            for (int j = 0; j < 4; j++) b[j] = Bs[k][tx * 4 + j];
            #pragma unroll
            for (int i = 0; i < 4; i++)
                #pragma unroll
                for (int j = 0; j < 4; j++)
                    acc[i][j] = fmaf(a[i], b[j], acc[i][j]);
        }
        __syncthreads();
    }
    #pragma unroll
    for (int i = 0; i < 4; i++) {
        int gm = m0 + ty * 4 + i;
        if (gm >= M) continue;
        #pragma unroll
        for (int j = 0; j < 4; j++) {
            int gn = n0 + tx * 4 + j;
            if (gn >= N) continue;
            float v = alpha * acc[i][j];
            if (BIAS) v += bias[gn];
            if (RES)  v += beta * Rp[(long)gm * N + gn];
            if (RELU) v = fmaxf(v, 0.f);
            Cm[(long)gm * N + gn] = v;
        }
    }
}

// ---------------- rmsnorm: one warp per token ----------------
__global__ __launch_bounds__(256)
void rmsnorm_k(const float* __restrict__ x, const float* __restrict__ scale,
               float* __restrict__ out)
{
    int warp = threadIdx.x >> 5, lane = threadIdx.x & 31;
    long t = (long)blockIdx.x * 8 + warp;
    const float* xr = x + t * Cc;
    float v[12], ss = 0.f;
    #pragma unroll
    for (int i = 0; i < 12; i++) { v[i] = xr[lane + i * 32]; ss += v[i] * v[i]; }
    #pragma unroll
    for (int o = 16; o > 0; o >>= 1) ss += __shfl_xor_sync(0xffffffffu, ss, o);
    float inv = rsqrtf(ss * (1.0f / Cc) + 1e-6f);
    float* orow = out + t * Cc;
    #pragma unroll
    for (int i = 0; i < 12; i++) orow[lane + i * 32] = v[i] * inv * scale[lane + i * 32];
}

// ---------------- frobenius norm (rsqrt) of the two orth weight matrices ----------------
__global__ void fro_k(const float* __restrict__ W0, const float* __restrict__ W1,
                      float* __restrict__ outsc)
{
    const float* W = blockIdx.x ? W1 : W0;
    __shared__ float red[32];
    float ss = 0.f;
    for (int i = threadIdx.x; i < Cc * Cc; i += 1024) { float w = W[i]; ss += w * w; }
    #pragma unroll
    for (int o = 16; o > 0; o >>= 1) ss += __shfl_xor_sync(0xffffffffu, ss, o);
    if ((threadIdx.x & 31) == 0) red[threadIdx.x >> 5] = ss;
    __syncthreads();
    if (threadIdx.x < 32) {
        float s2 = red[threadIdx.x];
        #pragma unroll
        for (int o = 16; o > 0; o >>= 1) s2 += __shfl_xor_sync(0xffffffffu, s2, o);
        if (threadIdx.x == 0) outsc[blockIdx.x] = rsqrtf(s2);
    }
}

__global__ void scale_k(const float* __restrict__ Win, const float* __restrict__ Wout,
                        const float* __restrict__ sc, float* __restrict__ X)
{
    int i = blockIdx.x * 256 + threadIdx.x;
    if (i < Cc * Cc)            X[i] = Win[i] * sc[0];
    else if (i < 2 * Cc * Cc)   X[i] = Wout[i - Cc * Cc] * sc[1];
}

// ---------------- pack Wq/Wk/Wv [H,C,HS] -> Wqkv [C, 3C] ----------------
__global__ void pack_k(const float* __restrict__ Wq, const float* __restrict__ Wk,
                       const float* __restrict__ Wv, float* __restrict__ Wqkv)
{
    int i = blockIdx.x * 256 + threadIdx.x;
    if (i >= Hh * Cc * HSs) return;
    int h = i / (Cc * HSs);
    int rem = i % (Cc * HSs);
    int c = rem / HSs, d = rem % HSs;
    long row = (long)c * C3;
    Wqkv[row +           h * HSs + d] = Wq[i];
    Wqkv[row + Cc      + h * HSs + d] = Wk[i];
    Wqkv[row + 2 * Cc  + h * HSs + d] = Wv[i];
}

// ---------------- causal flash attention, fp32 ----------------
// grid: (qtile=4, H=6, B=256), 256 threads. q tile 64 rows x 64 dims.
__global__ __launch_bounds__(256)
void flash_k(const float* __restrict__ qkv, float* __restrict__ attn)
{
    extern __shared__ float sm[];
    float* qs = sm;              // 64*65
    float* ks = qs + 64 * 65;
    float* vs = ks + 64 * 65;
    float* ps = vs + 64 * 65;

    int qt = blockIdx.x, h = blockIdx.y, b = blockIdx.z;
    int tid = threadIdx.x;
    int r = tid >> 2;            // query row 0..63
    int cg = tid & 3;            // 16-wide column group
    const float qscale = 0.125f; // HS^-0.5

    long base = (long)b * Tt * C3;
    for (int i = tid; i < 64 * 64; i += 256) {
        int row = i >> 6, d = i & 63;
        qs[row * 65 + d] = qkv[base + (long)(qt * 64 + row) * C3 + h * HSs + d] * qscale;
    }

    float o[16];
    #pragma unroll
    for (int i = 0; i < 16; i++) o[i] = 0.f;
    float m = -1e30f, l = 0.f;

    for (int kt = 0; kt <= qt; kt++) {
        __syncthreads();         // qs ready (1st iter); ks/vs/ps free (later iters)
        for (int i = tid; i < 64 * 64; i += 256) {
            int row = i >> 6, d = i & 63;
            long off = base + (long)(kt * 64 + row) * C3 + h * HSs + d;
            ks[row * 65 + d] = qkv[off + Cc];
            vs[row * 65 + d] = qkv[off + 2 * Cc];
        }
        __syncthreads();

        float s[16];
        #pragma unroll
        for (int cc = 0; cc < 16; cc++) {
            int c = cg * 16 + cc;
            float acc = 0.f;
            #pragma unroll
            for (int d = 0; d < 64; d++) acc = fmaf(qs[r * 65 + d], ks[c * 65 + d], acc);
            s[cc] = acc;
        }
        if (kt == qt) {
            #pragma unroll
            for (int cc = 0; cc < 16; cc++)
                if (cg * 16 + cc > r) s[cc] = -1e30f;
        }
        float mx = s[0];
        #pragma unroll
        for (int cc = 1; cc < 16; cc++) mx = fmaxf(mx, s[cc]);
        mx = fmaxf(mx, __shfl_xor_sync(0xffffffffu, mx, 1));
        mx = fmaxf(mx, __shfl_xor_sync(0xffffffffu, mx, 2));
        float mnew = fmaxf(m, mx);
        float corr = __expf(m - mnew);
        float rs = 0.f;
        #pragma unroll
        for (int cc = 0; cc < 16; cc++) { float p = __expf(s[cc] - mnew); s[cc] = p; rs += p; }
        rs += __shfl_xor_sync(0xffffffffu, rs, 1);
        rs += __shfl_xor_sync(0xffffffffu, rs, 2);
        l = l * corr + rs;
        m = mnew;
        #pragma unroll
        for (int i = 0; i < 16; i++) o[i] *= corr;
        #pragma unroll
        for (int cc = 0; cc < 16; cc++) ps[r * 65 + cg * 16 + cc] = s[cc];
        __syncthreads();
        #pragma unroll
        for (int c = 0; c < 64; c++) {
            float p = ps[r * 65 + c];
            #pragma unroll
            for (int dd = 0; dd < 16; dd++)
                o[dd] = fmaf(p, vs[c * 65 + cg * 16 + dd], o[dd]);
        }
    }
    float inv = 1.f / l;
    long obase = ((long)b * Tt + qt * 64 + r) * Cc + h * HSs + cg * 16;
    #pragma unroll
    for (int dd = 0; dd < 16; dd++) attn[obase + dd] = o[dd] * inv;
}

// ---------------- host side ----------------
static float* symaddr(const void* sym) {
    void* p = nullptr;
    cudaGetSymbolAddress(&p, sym);
    return (float*)p;
}

extern "C" void kernel_launch(void* const* d_in, const int* in_sizes, int n_in,
                              void* d_out, int out_size)
{
    const float* x      = (const float*)d_in[0];
    const float* Wq     = (const float*)d_in[1];
    const float* Wk     = (const float*)d_in[2];
    const float* Wv     = (const float*)d_in[3];
    const float* Wp     = (const float*)d_in[4];
    const float* bp     = (const float*)d_in[5];
    const float* scale1 = (const float*)d_in[6];
    const float* scale2 = (const float*)d_in[7];
    const float* W1     = (const float*)d_in[8];
    const float* b1     = (const float*)d_in[9];
    const float* W2     = (const float*)d_in[10];
    const float* b2     = (const float*)d_in[11];
    const float* Wo_in  = (const float*)d_in[12];
    const float* Wo_out = (const float*)d_in[13];
    float* out = (float*)d_out;

    float* h1   = symaddr(g_h1);
    float* qkv  = symaddr(g_qkv);
    float* attn = symaddr(g_attn);
    float* h2   = symaddr(g_h2);
    float* h3   = symaddr(g_h3);
    float* h4   = symaddr(g_h4);
    float* ff   = symaddr(g_ff);
    float* h6   = symaddr(g_h6);
    float* X0   = symaddr(g_X0);
    float* X1   = symaddr(g_X1);
    float* Tm   = symaddr(g_Tm);
    float* Wqkv = symaddr(g_Wqkv);
    float* sc   = symaddr(g_sc);

    cudaFuncSetAttribute(flash_k, cudaFuncAttributeMaxDynamicSharedMemorySize, 4 * 64 * 65 * 4);

    const long MS = (long)Cc * Cc;  // 384*384 batch stride

    // ---- orth(Wo_in), orth(Wo_out) via Newton-Schulz polar iteration (batched 2) ----
    fro_k<<<2, 1024>>>(Wo_in, Wo_out, sc);
    scale_k<<<(2 * Cc * Cc + 255) / 256, 256>>>(Wo_in, Wo_out, sc, X0);
    dim3 gs(6, 6, 2);
    float* Xc = X0;
    float* Xn = X1;
    for (int it = 0; it < NS_ITERS; it++) {
        // Tm = Xc @ Xc^T
        gemm_k<true, false, false, false><<<gs, 256>>>(
            Xc, Xc, nullptr, nullptr, Tm, Cc, Cc, Cc, 1.f, 0.f, MS, MS, MS);
        // Xn = 1.5*Xc - 0.5 * Tm @ Xc
        gemm_k<false, false, false, true><<<gs, 256>>>(
            Tm, Xc, nullptr, Xc, Xn, Cc, Cc, Cc, -0.5f, 1.5f, MS, MS, MS);
        float* t = Xc; Xc = Xn; Xn = t;
    }
    const float* O_in  = Xc;
    const float* O_out = Xc + MS;

    // ---- weights pack + ln1 ----
    pack_k<<<(Hh * Cc * HSs + 255) / 256, 256>>>(Wq, Wk, Wv, Wqkv);
    rmsnorm_k<<<BT / 8, 256>>>(x, scale1, h1);

    // ---- qkv = h1 @ Wqkv  [BT x 1152] ----
    gemm_k<false, false, false, false><<<dim3(C3 / 64, BT / 64, 1), 256>>>(
        h1, Wqkv, nullptr, nullptr, qkv, BT, C3, Cc, 1.f, 0.f, 0, 0, 0);

    // ---- attention ----
    flash_k<<<dim3(Tt / 64, Hh, Bb), 256, 4 * 64 * 65 * 4>>>(qkv, attn);

    // ---- h2 = attn @ Wp + bp + h1 ----
    gemm_k<false, false, true, true><<<dim3(Cc / 64, BT / 64, 1), 256>>>(
        attn, Wp, bp, h1, h2, BT, Cc, Cc, 1.f, 1.f, 0, 0, 0);

    // ---- ln2 ----
    rmsnorm_k<<<BT / 8, 256>>>(h2, scale2, h3);

    // ---- h4 = h3 @ O_in ----
    gemm_k<false, false, false, false><<<dim3(Cc / 64, BT / 64, 1), 256>>>(
        h3, O_in, nullptr, nullptr, h4, BT, Cc, Cc, 1.f, 0.f, 0, 0, 0);

    // ---- ff = relu(h4 @ W1 + b1)  [BT x 307] ----
    gemm_k<false, true, true, false><<<dim3((Pp + 63) / 64, BT / 64, 1), 256>>>(
        h4, W1, b1, nullptr, ff, BT, Pp, Cc, 1.f, 0.f, 0, 0, 0);

    // ---- h6 = ff @ W2 + b2 ----
    gemm_k<false, false, true, false><<<dim3(Cc / 64, BT / 64, 1), 256>>>(
        ff, W2, b2, nullptr, h6, BT, Cc, Pp, 1.f, 0.f, 0, 0, 0);

    // ---- out = h6 @ O_out + h6 ----
    gemm_k<false, false, false, true><<<dim3(Cc / 64, BT / 64, 1), 256>>>(
        h6, O_out, nullptr, h6, out, BT, Cc, Cc, 1.f, 1.f, 0, 0, 0);

    (void)in_sizes; (void)n_in; (void)out_size;
}

// round 2
// speedup vs baseline: 1.3400x; 1.3400x over previous
#include <cuda_runtime.h>

#define Bb  256
#define Tt  256
#define Cc  384
#define Hh  6
#define HSs 64
#define Pp  307
#define PPAD 320
#define BT  (Bb*Tt)            // 65536 tokens
#define C3  (3*Cc)             // 1152
#define NS_ITERS 36
#define NS_CTAS 144
#define MSZ (Cc*Cc)            // 147456

// ---------------- scratch (device globals; no allocation at runtime) ----------------
__device__ float g_h1  [(size_t)BT*Cc];
__device__ float g_qkv [(size_t)BT*C3];
__device__ float g_attn[(size_t)BT*Cc];
__device__ float g_h2  [(size_t)BT*Cc];
__device__ float g_h3  [(size_t)BT*Cc];
__device__ float g_h4  [(size_t)BT*Cc];
__device__ float g_ff  [(size_t)BT*PPAD];
__device__ float g_h6  [(size_t)BT*Cc];
__device__ float g_X0  [2*MSZ];
__device__ float g_X1  [2*MSZ];
__device__ float g_Tm  [2*MSZ];
__device__ float g_Wqkv[Cc*C3];
__device__ float g_part[NS_CTAS];
__device__ unsigned g_barCnt;
__device__ unsigned g_barGen;

// ================= software grid barrier (all NS_CTAS CTAs co-resident) =================
__device__ __forceinline__ void gridbar() {
    __syncthreads();
    if (threadIdx.x == 0) {
        __threadfence();
        volatile unsigned* vg = &g_barGen;
        unsigned gen = *vg;
        unsigned old = atomicAdd(&g_barCnt, 1u);
        if (old == NS_CTAS - 1) {
            g_barCnt = 0;
            __threadfence();
            *vg = gen + 1;
        } else {
            while (*vg == gen) { }
        }
        __threadfence();
    }
    __syncthreads();
}

// ================= persistent Newton-Schulz polar orthogonalization =================
// grid = 144 CTAs x 256 thr. Per matrix (2): 72 tiles of 32x64.
__global__ __launch_bounds__(256)
void ns_k(const float* __restrict__ Win, const float* __restrict__ Wout)
{
    int bx = blockIdx.x, tid = threadIdx.x;
    int lane = tid & 31, wid = tid >> 5;
    int b  = bx / 72;
    int t  = bx % 72;
    int tm = t / 6;      // 0..11 (32-row band)
    int tn = t % 6;      // 0..5  (64-col band)
    int ty = tid >> 4;   // 0..15 -> 2 rows each
    int tx = tid & 15;   // 0..15 -> 4 cols each

    __shared__ float As[16][36];
    __shared__ float Bs[16][72];
    __shared__ float red[8];
    __shared__ float ssc[2];

    const float* W = b ? Wout : Win;

    // ---- phase 0: partial frobenius sums (CTA slice of 2048 elems) ----
    {
        long off = (long)t * 2048;
        float ss = 0.f;
        #pragma unroll
        for (int i = 0; i < 8; i++) { float w = W[off + tid + i * 256]; ss += w * w; }
        #pragma unroll
        for (int o = 16; o > 0; o >>= 1) ss += __shfl_xor_sync(0xffffffffu, ss, o);
        if (lane == 0) red[wid] = ss;
        __syncthreads();
        if (tid == 0) {
            float s = 0.f;
            #pragma unroll
            for (int i = 0; i < 8; i++) s += red[i];
            __stcg(&g_part[bx], s);
        }
    }
    gridbar();

    // ---- scales (deterministic fixed-order sums) ----
    if (tid < 2) {
        float s = 0.f;
        for (int i = 0; i < 72; i++) s += __ldcg(&g_part[tid * 72 + i]);
        ssc[tid] = rsqrtf(s);
    }
    __syncthreads();
    float rs = ssc[b];

    // ---- X0 = W * rs ----
    {
        long off = (long)t * 2048;
        #pragma unroll
        for (int i = 0; i < 8; i++)
            __stcg(&g_X0[(long)b * MSZ + off + tid + i * 256], W[off + tid + i * 256] * rs);
    }
    gridbar();

    float* Xc = g_X0;
    float* Xn = g_X1;

    for (int it = 0; it < NS_ITERS; it++) {
        const float* X = Xc + (long)b * MSZ;
        float* T       = g_Tm + (long)b * MSZ;

        // ---- phase A: T tile = X @ X^T  (tile rows tm*32, cols tn*64) ----
        float acc[2][4] = {};
        for (int k0 = 0; k0 < Cc; k0 += 16) {
            if (tid < 128) {
                int r = tid >> 2, q = tid & 3;
                float4 v = __ldcg((const float4*)(X + (long)(tm * 32 + r) * Cc + k0 + q * 4));
                As[q*4+0][r] = v.x; As[q*4+1][r] = v.y; As[q*4+2][r] = v.z; As[q*4+3][r] = v.w;
            }
            {
                int r = tid >> 2, q = tid & 3;
                float4 v = __ldcg((const float4*)(X + (long)(tn * 64 + r) * Cc + k0 + q * 4));
                Bs[q*4+0][r] = v.x; Bs[q*4+1][r] = v.y; Bs[q*4+2][r] = v.z; Bs[q*4+3][r] = v.w;
            }
            __syncthreads();
            #pragma unroll
            for (int k = 0; k < 16; k++) {
                float a0 = As[k][ty*2], a1 = As[k][ty*2+1];
                float b0 = Bs[k][tx*4], b1 = Bs[k][tx*4+1], b2 = Bs[k][tx*4+2], b3 = Bs[k][tx*4+3];
                acc[0][0] = fmaf(a0,b0,acc[0][0]); acc[0][1] = fmaf(a0,b1,acc[0][1]);
                acc[0][2] = fmaf(a0,b2,acc[0][2]); acc[0][3] = fmaf(a0,b3,acc[0][3]);
                acc[1][0] = fmaf(a1,b0,acc[1][0]); acc[1][1] = fmaf(a1,b1,acc[1][1]);
                acc[1][2] = fmaf(a1,b2,acc[1][2]); acc[1][3] = fmaf(a1,b3,acc[1][3]);
            }
            __syncthreads();
        }
        #pragma unroll
        for (int i = 0; i < 2; i++)
            #pragma unroll
            for (int j = 0; j < 4; j++)
                __stcg(&T[(long)(tm * 32 + ty * 2 + i) * Cc + tn * 64 + tx * 4 + j], acc[i][j]);
        gridbar();

        // ---- phase B: Xn = 1.5*X - 0.5 * T @ X ----
        float ac2[2][4] = {};
        for (int k0 = 0; k0 < Cc; k0 += 16) {
            if (tid < 128) {
                int r = tid >> 2, q = tid & 3;
                float4 v = __ldcg((const float4*)(T + (long)(tm * 32 + r) * Cc + k0 + q * 4));
                As[q*4+0][r] = v.x; As[q*4+1][r] = v.y; As[q*4+2][r] = v.z; As[q*4+3][r] = v.w;
            }
            {
                int kk = tid >> 4, n4 = tid & 15;
                float4 v = __ldcg((const float4*)(X + (long)(k0 + kk) * Cc + tn * 64 + n4 * 4));
                Bs[kk][n4*4+0] = v.x; Bs[kk][n4*4+1] = v.y; Bs[kk][n4*4+2] = v.z; Bs[kk][n4*4+3] = v.w;
            }
            __syncthreads();
            #pragma unroll
            for (int k = 0; k < 16; k++) {
                float a0 = As[k][ty*2], a1 = As[k][ty*2+1];
                float b0 = Bs[k][tx*4], b1 = Bs[k][tx*4+1], b2 = Bs[k][tx*4+2], b3 = Bs[k][tx*4+3];
                ac2[0][0] = fmaf(a0,b0,ac2[0][0]); ac2[0][1] = fmaf(a0,b1,ac2[0][1]);
                ac2[0][2] = fmaf(a0,b2,ac2[0][2]); ac2[0][3] = fmaf(a0,b3,ac2[0][3]);
                ac2[1][0] = fmaf(a1,b0,ac2[1][0]); ac2[1][1] = fmaf(a1,b1,ac2[1][1]);
                ac2[1][2] = fmaf(a1,b2,ac2[1][2]); ac2[1][3] = fmaf(a1,b3,ac2[1][3]);
            }
            __syncthreads();
        }
        {
            float* Xnb = Xn + (long)b * MSZ;
            #pragma unroll
            for (int i = 0; i < 2; i++)
                #pragma unroll
                for (int j = 0; j < 4; j++) {
                    long idx = (long)(tm * 32 + ty * 2 + i) * Cc + tn * 64 + tx * 4 + j;
                    float xv = __ldcg(&X[idx]);
                    __stcg(&Xnb[idx], 1.5f * xv - 0.5f * ac2[i][j]);
                }
        }
        gridbar();
        float* tp = Xc; Xc = Xn; Xn = tp;
    }
    // NS_ITERS even -> final result resides in g_X0
}

// ================= tf32 tensor-core GEMM =================
__device__ __forceinline__ unsigned f2tf32(float f) {
    unsigned u; asm("cvt.rna.tf32.f32 %0, %1;" : "=r"(u) : "f"(f)); return u;
}
__device__ __forceinline__ void mma8(float* c, unsigned a0, unsigned a1, unsigned a2, unsigned a3,
                                     unsigned b0, unsigned b1) {
    asm volatile(
        "mma.sync.aligned.m16n8k8.row.col.f32.tf32.tf32.f32 "
        "{%0,%1,%2,%3}, {%4,%5,%6,%7}, {%8,%9}, {%0,%1,%2,%3};"
        : "+f"(c[0]), "+f"(c[1]), "+f"(c[2]), "+f"(c[3])
        : "r"(a0), "r"(a1), "r"(a2), "r"(a3), "r"(b0), "r"(b1));
}

// C[M x Nstore] = A[M x K](lda) @ B[K x Nreal](ldb, zero-padded beyond Nreal/Kb)
// (+bias, +Res, relu). BM=128 BN=64 BK=16; grid=(Nstore/64, M/128); 256 thr.
template<bool RELU, bool BIAS, bool RES>
__global__ __launch_bounds__(256)
void gemm_tc(const float* __restrict__ A, const float* __restrict__ B,
             const float* __restrict__ bias, const float* __restrict__ Res,
             float* __restrict__ C,
             int Nstore, int K, int lda, int ldb, int Nreal, int Kb)
{
    __shared__ unsigned As[2][128][20];   // [m][k] tf32
    __shared__ unsigned Bsm[2][16][72];   // [k][n] tf32
    int tid = threadIdx.x;
    int lane = tid & 31, wid = tid >> 5;
    int wm = wid & 3, wn = wid >> 2;      // warp tile: rows wm*32, cols wn*32
    long m0 = (long)blockIdx.y * 128;
    int n0 = blockIdx.x * 64;

    int ar = tid >> 2;                    // 0..63 ; handles rows ar, ar+64
    int aq = tid & 3;                     // k quarter
    int bk = tid >> 4;                    // 0..15
    int bn = tid & 15;

    float acc[2][4][4];
    #pragma unroll
    for (int i = 0; i < 2; i++)
        #pragma unroll
        for (int j = 0; j < 4; j++)
            #pragma unroll
            for (int e = 0; e < 4; e++) acc[i][j][e] = 0.f;

    int nk = K / 16;

    // prologue: tile 0 -> buf 0
    {
        #pragma unroll
        for (int h = 0; h < 2; h++) {
            int row = ar + h * 64;
            float4 v = *(const float4*)(A + (m0 + row) * lda + aq * 4);
            uint4 u = { f2tf32(v.x), f2tf32(v.y), f2tf32(v.z), f2tf32(v.w) };
            *(uint4*)&As[0][row][aq * 4] = u;
        }
        #pragma unroll
        for (int j = 0; j < 4; j++) {
            int n = bn + j * 16;
            int gn = n0 + n;
            float v = 0.f;
            if (bk < Kb && gn < Nreal) v = B[(long)bk * ldb + gn];
            Bsm[0][bk][n] = f2tf32(v);
        }
    }
    __syncthreads();

    int gr = lane >> 2, tg = lane & 3;

    for (int kt = 0; kt < nk; kt++) {
        int cur = kt & 1, nxt = cur ^ 1;
        bool more = (kt + 1 < nk);
        float4 ra[2];
        float rb[4];
        if (more) {
            int k0 = (kt + 1) * 16;
            #pragma unroll
            for (int h = 0; h < 2; h++) {
                int row = ar + h * 64;
                ra[h] = *(const float4*)(A + (m0 + row) * lda + k0 + aq * 4);
            }
            #pragma unroll
            for (int j = 0; j < 4; j++) {
                int n = bn + j * 16;
                int gk = k0 + bk, gn = n0 + n;
                rb[j] = (gk < Kb && gn < Nreal) ? B[(long)gk * ldb + gn] : 0.f;
            }
        }

        #pragma unroll
        for (int ks = 0; ks < 2; ks++) {
            int kb = ks * 8;
            unsigned af[2][4], bf[4][2];
            #pragma unroll
            for (int mt = 0; mt < 2; mt++) {
                int mrow = wm * 32 + mt * 16;
                af[mt][0] = As[cur][mrow + gr    ][kb + tg    ];
                af[mt][1] = As[cur][mrow + gr + 8][kb + tg    ];
                af[mt][2] = As[cur][mrow + gr    ][kb + tg + 4];
                af[mt][3] = As[cur][mrow + gr + 8][kb + tg + 4];
            }
            #pragma unroll
            for (int nt = 0; nt < 4; nt++) {
                int ncol = wn * 32 + nt * 8;
                bf[nt][0] = Bsm[cur][kb + tg    ][ncol + gr];
                bf[nt][1] = Bsm[cur][kb + tg + 4][ncol + gr];
            }
            #pragma unroll
            for (int mt = 0; mt < 2; mt++)
                #pragma unroll
                for (int nt = 0; nt < 4; nt++)
                    mma8(acc[mt][nt], af[mt][0], af[mt][1], af[mt][2], af[mt][3],
                         bf[nt][0], bf[nt][1]);
        }

        if (more) {
            #pragma unroll
            for (int h = 0; h < 2; h++) {
                int row = ar + h * 64;
                uint4 u = { f2tf32(ra[h].x), f2tf32(ra[h].y), f2tf32(ra[h].z), f2tf32(ra[h].w) };
                *(uint4*)&As[nxt][row][aq * 4] = u;
            }
            #pragma unroll
            for (int j = 0; j < 4; j++) Bsm[nxt][bk][bn + j * 16] = f2tf32(rb[j]);
        }
        __syncthreads();
    }

    // epilogue
    #pragma unroll
    for (int mt = 0; mt < 2; mt++) {
        #pragma unroll
        for (int nt = 0; nt < 4; nt++) {
            int r0 = wm * 32 + mt * 16 + gr;
            int cb = n0 + wn * 32 + nt * 8 + 2 * tg;
            #pragma unroll
            for (int half = 0; half < 2; half++) {
                long gm = m0 + r0 + half * 8;
                float v0 = acc[mt][nt][half * 2 + 0];
                float v1 = acc[mt][nt][half * 2 + 1];
                if (BIAS) {
                    v0 += (cb     < Nreal) ? bias[cb]     : 0.f;
                    v1 += (cb + 1 < Nreal) ? bias[cb + 1] : 0.f;
                }
                if (RES) {
                    float2 rr = *(const float2*)(Res + gm * Nstore + cb);
                    v0 += rr.x; v1 += rr.y;
                }
                if (RELU) { v0 = fmaxf(v0, 0.f); v1 = fmaxf(v1, 0.f); }
                *(float2*)(C + gm * Nstore + cb) = make_float2(v0, v1);
            }
        }
    }
}

// ---------------- rmsnorm: one warp per token ----------------
__global__ __launch_bounds__(256)
void rmsnorm_k(const float* __restrict__ x, const float* __restrict__ scale,
               float* __restrict__ out)
{
    int warp = threadIdx.x >> 5, lane = threadIdx.x & 31;
    long t = (long)blockIdx.x * 8 + warp;
    const float* xr = x + t * Cc;
    float v[12], ss = 0.f;
    #pragma unroll
    for (int i = 0; i < 12; i++) { v[i] = xr[lane + i * 32]; ss += v[i] * v[i]; }
    #pragma unroll
    for (int o = 16; o > 0; o >>= 1) ss += __shfl_xor_sync(0xffffffffu, ss, o);
    float inv = rsqrtf(ss * (1.0f / Cc) + 1e-6f);
    float* orow = out + t * Cc;
    #pragma unroll
    for (int i = 0; i < 12; i++) orow[lane + i * 32] = v[i] * inv * scale[lane + i * 32];
}

// ---------------- pack Wq/Wk/Wv [H,C,HS] -> Wqkv [C, 3C] ----------------
__global__ void pack_k(const float* __restrict__ Wq, const float* __restrict__ Wk,
                       const float* __restrict__ Wv, float* __restrict__ Wqkv)
{
    int i = blockIdx.x * 256 + threadIdx.x;
    if (i >= Hh * Cc * HSs) return;
    int h = i / (Cc * HSs);
    int rem = i % (Cc * HSs);
    int c = rem / HSs, d = rem % HSs;
    long row = (long)c * C3;
    Wqkv[row +           h * HSs + d] = Wq[i];
    Wqkv[row + Cc      + h * HSs + d] = Wk[i];
    Wqkv[row + 2 * Cc  + h * HSs + d] = Wv[i];
}

// ---------------- causal flash attention, fp32 ----------------
__global__ __launch_bounds__(256)
void flash_k(const float* __restrict__ qkv, float* __restrict__ attn)
{
    extern __shared__ float sm[];
    float* qs = sm;              // 64*65
    float* ks = qs + 64 * 65;
    float* vs = ks + 64 * 65;
    float* ps = vs + 64 * 65;

    int qt = blockIdx.x, h = blockIdx.y, b = blockIdx.z;
    int tid = threadIdx.x;
    int r = tid >> 2;            // query row 0..63
    int cg = tid & 3;            // 16-wide column group
    const float qscale = 0.125f;

    long base = (long)b * Tt * C3;
    for (int i = tid; i < 64 * 64; i += 256) {
        int row = i >> 6, d = i & 63;
        qs[row * 65 + d] = qkv[base + (long)(qt * 64 + row) * C3 + h * HSs + d] * qscale;
    }

    float o[16];
    #pragma unroll
    for (int i = 0; i < 16; i++) o[i] = 0.f;
    float m = -1e30f, l = 0.f;

    for (int kt = 0; kt <= qt; kt++) {
        __syncthreads();
        for (int i = tid; i < 64 * 64; i += 256) {
            int row = i >> 6, d = i & 63;
            long off = base + (long)(kt * 64 + row) * C3 + h * HSs + d;
            ks[row * 65 + d] = qkv[off + Cc];
            vs[row * 65 + d] = qkv[off + 2 * Cc];
        }
        __syncthreads();

        float s[16];
        #pragma unroll
        for (int cc = 0; cc < 16; cc++) s[cc] = 0.f;
        for (int d0 = 0; d0 < 64; d0 += 8) {
            float qv[8];
            #pragma unroll
            for (int j = 0; j < 8; j++) qv[j] = qs[r * 65 + d0 + j];
            #pragma unroll
            for (int cc = 0; cc < 16; cc++) {
                int c = cg * 16 + cc;
                #pragma unroll
                for (int j = 0; j < 8; j++)
                    s[cc] = fmaf(qv[j], ks[c * 65 + d0 + j], s[cc]);
            }
        }
        if (kt == qt) {
            #pragma unroll
            for (int cc = 0; cc < 16; cc++)
                if (cg * 16 + cc > r) s[cc] = -1e30f;
        }
        float mx = s[0];
        #pragma unroll
        for (int cc = 1; cc < 16; cc++) mx = fmaxf(mx, s[cc]);
        mx = fmaxf(mx, __shfl_xor_sync(0xffffffffu, mx, 1));
        mx = fmaxf(mx, __shfl_xor_sync(0xffffffffu, mx, 2));
        float mnew = fmaxf(m, mx);
        float corr = __expf(m - mnew);
        float rs = 0.f;
        #pragma unroll
        for (int cc = 0; cc < 16; cc++) { float p = __expf(s[cc] - mnew); s[cc] = p; rs += p; }
        rs += __shfl_xor_sync(0xffffffffu, rs, 1);
        rs += __shfl_xor_sync(0xffffffffu, rs, 2);
        l = l * corr + rs;
        m = mnew;
        #pragma unroll
        for (int i = 0; i < 16; i++) o[i] *= corr;
        #pragma unroll
        for (int cc = 0; cc < 16; cc++) ps[r * 65 + cg * 16 + cc] = s[cc];
        __syncthreads();
        for (int c0 = 0; c0 < 64; c0 += 8) {
            float pv[8];
            #pragma unroll
            for (int j = 0; j < 8; j++) pv[j] = ps[r * 65 + c0 + j];
            #pragma unroll
            for (int dd = 0; dd < 16; dd++)
                #pragma unroll
                for (int j = 0; j < 8; j++)
                    o[dd] = fmaf(pv[j], vs[(c0 + j) * 65 + cg * 16 + dd], o[dd]);
        }
    }
    float inv = 1.f / l;
    long obase = ((long)b * Tt + qt * 64 + r) * Cc + h * HSs + cg * 16;
    #pragma unroll
    for (int dd = 0; dd < 16; dd++) attn[obase + dd] = o[dd] * inv;
}

// ---------------- host side ----------------
static float* symaddr(const void* sym) {
    void* p = nullptr;
    cudaGetSymbolAddress(&p, sym);
    return (float*)p;
}

extern "C" void kernel_launch(void* const* d_in, const int* in_sizes, int n_in,
                              void* d_out, int out_size)
{
    const float* x      = (const float*)d_in[0];
    const float* Wq     = (const float*)d_in[1];
    const float* Wk     = (const float*)d_in[2];
    const float* Wv     = (const float*)d_in[3];
    const float* Wp     = (const float*)d_in[4];
    const float* bp     = (const float*)d_in[5];
    const float* scale1 = (const float*)d_in[6];
    const float* scale2 = (const float*)d_in[7];
    const float* W1     = (const float*)d_in[8];
    const float* b1     = (const float*)d_in[9];
    const float* W2     = (const float*)d_in[10];
    const float* b2     = (const float*)d_in[11];
    const float* Wo_in  = (const float*)d_in[12];
    const float* Wo_out = (const float*)d_in[13];
    float* out = (float*)d_out;

    float* h1   = symaddr(g_h1);
    float* qkv  = symaddr(g_qkv);
    float* attn = symaddr(g_attn);
    float* h2   = symaddr(g_h2);
    float* h3   = symaddr(g_h3);
    float* h4   = symaddr(g_h4);
    float* ff   = symaddr(g_ff);
    float* h6   = symaddr(g_h6);
    float* X0   = symaddr(g_X0);
    float* Wqkv = symaddr(g_Wqkv);

    cudaFuncSetAttribute(flash_k, cudaFuncAttributeMaxDynamicSharedMemorySize, 4 * 64 * 65 * 4);

    // ---- orth via persistent Newton-Schulz (single launch) ----
    ns_k<<<NS_CTAS, 256>>>(Wo_in, Wo_out);
    const float* O_in  = X0;
    const float* O_out = X0 + MSZ;

    // ---- pack + ln1 ----
    pack_k<<<(Hh * Cc * HSs + 255) / 256, 256>>>(Wq, Wk, Wv, Wqkv);
    rmsnorm_k<<<BT / 8, 256>>>(x, scale1, h1);

    // ---- qkv = h1 @ Wqkv ----
    gemm_tc<false, false, false><<<dim3(C3 / 64, BT / 128), 256>>>(
        h1, Wqkv, nullptr, nullptr, qkv, C3, Cc, Cc, C3, C3, Cc);

    // ---- attention ----
    flash_k<<<dim3(Tt / 64, Hh, Bb), 256, 4 * 64 * 65 * 4>>>(qkv, attn);

    // ---- h2 = attn @ Wp + bp + h1 ----
    gemm_tc<false, true, true><<<dim3(Cc / 64, BT / 128), 256>>>(
        attn, Wp, bp, h1, h2, Cc, Cc, Cc, Cc, Cc, Cc);

    // ---- ln2 ----
    rmsnorm_k<<<BT / 8, 256>>>(h2, scale2, h3);

    // ---- h4 = h3 @ O_in ----
    gemm_tc<false, false, false><<<dim3(Cc / 64, BT / 128), 256>>>(
        h3, O_in, nullptr, nullptr, h4, Cc, Cc, Cc, Cc, Cc, Cc);

    // ---- ff = relu(h4 @ W1 + b1)  stored padded to 320 cols (pad = 0) ----
    gemm_tc<true, true, false><<<dim3(PPAD / 64, BT / 128), 256>>>(
        h4, W1, b1, nullptr, ff, PPAD, Cc, Cc, Pp, Pp, Cc);

    // ---- h6 = ff @ W2 + b2  (K padded to 320, B guarded to 307 rows) ----
    gemm_tc<false, true, false><<<dim3(Cc / 64, BT / 128), 256>>>(
        ff, W2, b2, nullptr, h6, Cc, PPAD, PPAD, Cc, Cc, Pp);

    // ---- out = h6 @ O_out + h6 ----
    gemm_tc<false, false, true><<<dim3(Cc / 64, BT / 128), 256>>>(
        h6, O_out, nullptr, h6, out, Cc, Cc, Cc, Cc, Cc, Cc);

    (void)in_sizes; (void)n_in; (void)out_size;
}

// round 4
// speedup vs baseline: 3.3001x; 2.4628x over previous
#include <cuda_runtime.h>

#define Bb  256
#define Tt  256
#define Cc  384
#define Hh  6
#define HSs 64
#define Pp  307
#define PPAD 320
#define BT  (Bb*Tt)            // 65536 tokens
#define C3  (3*Cc)             // 1152
#define NS_ITERS 36
#define NS_CTAS 144
#define MSZ (Cc*Cc)            // 147456
#define FPQ 68
#define FPV 72

// ---------------- scratch (device globals; no allocation at runtime) ----------------
__device__ float g_h1  [(size_t)BT*Cc];
__device__ float g_qkv [(size_t)BT*C3];
__device__ float g_attn[(size_t)BT*Cc];
__device__ float g_h2  [(size_t)BT*Cc];
__device__ float g_h3  [(size_t)BT*Cc];
__device__ float g_h4  [(size_t)BT*Cc];
__device__ float g_ff  [(size_t)BT*PPAD];
__device__ float g_h6  [(size_t)BT*Cc];
__device__ float g_X0  [2*MSZ];
__device__ float g_X1  [2*MSZ];
__device__ float g_Tm  [2*MSZ];
__device__ float g_Wqkv[Cc*C3];
__device__ float g_part[NS_CTAS];
__device__ unsigned g_barCnt;
__device__ unsigned g_barGen;

// ================= software grid barrier =================
__device__ __forceinline__ void gridbar() {
    __syncthreads();
    if (threadIdx.x == 0) {
        __threadfence();
        volatile unsigned* vg = &g_barGen;
        unsigned gen = *vg;
        unsigned old = atomicAdd(&g_barCnt, 1u);
        if (old == NS_CTAS - 1) {
            g_barCnt = 0;
            __threadfence();
            *vg = gen + 1;
        } else {
            while (*vg == gen) { }
        }
        __threadfence();
    }
    __syncthreads();
}

// ================= persistent Newton-Schulz polar orthogonalization =================
__global__ __launch_bounds__(256)
void ns_k(const float* __restrict__ Win, const float* __restrict__ Wout)
{
    int bx = blockIdx.x, tid = threadIdx.x;
    int lane = tid & 31, wid = tid >> 5;
    int b  = bx / 72;
    int t  = bx % 72;
    int tm = t / 6;
    int tn = t % 6;
    int ty = tid >> 4;
    int tx = tid & 15;

    __shared__ float As[16][36];
    __shared__ float Bs[16][72];
    __shared__ float red[8];
    __shared__ float ssc[2];

    const float* W = b ? Wout : Win;

    {
        long off = (long)t * 2048;
        float ss = 0.f;
        #pragma unroll
        for (int i = 0; i < 8; i++) { float w = W[off + tid + i * 256]; ss += w * w; }
        #pragma unroll
        for (int o = 16; o > 0; o >>= 1) ss += __shfl_xor_sync(0xffffffffu, ss, o);
        if (lane == 0) red[wid] = ss;
        __syncthreads();
        if (tid == 0) {
            float s = 0.f;
            #pragma unroll
            for (int i = 0; i < 8; i++) s += red[i];
            __stcg(&g_part[bx], s);
        }
    }
    gridbar();

    if (tid < 2) {
        float s = 0.f;
        for (int i = 0; i < 72; i++) s += __ldcg(&g_part[tid * 72 + i]);
        ssc[tid] = rsqrtf(s);
    }
    __syncthreads();
    float rs = ssc[b];

    {
        long off = (long)t * 2048;
        #pragma unroll
        for (int i = 0; i < 8; i++)
            __stcg(&g_X0[(long)b * MSZ + off + tid + i * 256], W[off + tid + i * 256] * rs);
    }
    gridbar();

    float* Xc = g_X0;
    float* Xn = g_X1;

    for (int it = 0; it < NS_ITERS; it++) {
        const float* X = Xc + (long)b * MSZ;
        float* T       = g_Tm + (long)b * MSZ;

        float acc[2][4] = {};
        for (int k0 = 0; k0 < Cc; k0 += 16) {
            if (tid < 128) {
                int r = tid >> 2, q = tid & 3;
                float4 v = __ldcg((const float4*)(X + (long)(tm * 32 + r) * Cc + k0 + q * 4));
                As[q*4+0][r] = v.x; As[q*4+1][r] = v.y; As[q*4+2][r] = v.z; As[q*4+3][r] = v.w;
            }
            {
                int r = tid >> 2, q = tid & 3;
                float4 v = __ldcg((const float4*)(X + (long)(tn * 64 + r) * Cc + k0 + q * 4));
                Bs[q*4+0][r] = v.x; Bs[q*4+1][r] = v.y; Bs[q*4+2][r] = v.z; Bs[q*4+3][r] = v.w;
            }
            __syncthreads();
            #pragma unroll
            for (int k = 0; k < 16; k++) {
                float a0 = As[k][ty*2], a1 = As[k][ty*2+1];
                float b0 = Bs[k][tx*4], b1 = Bs[k][tx*4+1], b2 = Bs[k][tx*4+2], b3 = Bs[k][tx*4+3];
                acc[0][0] = fmaf(a0,b0,acc[0][0]); acc[0][1] = fmaf(a0,b1,acc[0][1]);
                acc[0][2] = fmaf(a0,b2,acc[0][2]); acc[0][3] = fmaf(a0,b3,acc[0][3]);
                acc[1][0] = fmaf(a1,b0,acc[1][0]); acc[1][1] = fmaf(a1,b1,acc[1][1]);
                acc[1][2] = fmaf(a1,b2,acc[1][2]); acc[1][3] = fmaf(a1,b3,acc[1][3]);
            }
            __syncthreads();
        }
        #pragma unroll
        for (int i = 0; i < 2; i++)
            #pragma unroll
            for (int j = 0; j < 4; j++)
                __stcg(&T[(long)(tm * 32 + ty * 2 + i) * Cc + tn * 64 + tx * 4 + j], acc[i][j]);
        gridbar();

        float ac2[2][4] = {};
        for (int k0 = 0; k0 < Cc; k0 += 16) {
            if (tid < 128) {
                int r = tid >> 2, q = tid & 3;
                float4 v = __ldcg((const float4*)(T + (long)(tm * 32 + r) * Cc + k0 + q * 4));
                As[q*4+0][r] = v.x; As[q*4+1][r] = v.y; As[q*4+2][r] = v.z; As[q*4+3][r] = v.w;
            }
            {
                int kk = tid >> 4, n4 = tid & 15;
                float4 v = __ldcg((const float4*)(X + (long)(k0 + kk) * Cc + tn * 64 + n4 * 4));
                Bs[kk][n4*4+0] = v.x; Bs[kk][n4*4+1] = v.y; Bs[kk][n4*4+2] = v.z; Bs[kk][n4*4+3] = v.w;
            }
            __syncthreads();
            #pragma unroll
            for (int k = 0; k < 16; k++) {
                float a0 = As[k][ty*2], a1 = As[k][ty*2+1];
                float b0 = Bs[k][tx*4], b1 = Bs[k][tx*4+1], b2 = Bs[k][tx*4+2], b3 = Bs[k][tx*4+3];
                ac2[0][0] = fmaf(a0,b0,ac2[0][0]); ac2[0][1] = fmaf(a0,b1,ac2[0][1]);
                ac2[0][2] = fmaf(a0,b2,ac2[0][2]); ac2[0][3] = fmaf(a0,b3,ac2[0][3]);
                ac2[1][0] = fmaf(a1,b0,ac2[1][0]); ac2[1][1] = fmaf(a1,b1,ac2[1][1]);
                ac2[1][2] = fmaf(a1,b2,ac2[1][2]); ac2[1][3] = fmaf(a1,b3,ac2[1][3]);
            }
            __syncthreads();
        }
        {
            float* Xnb = Xn + (long)b * MSZ;
            #pragma unroll
            for (int i = 0; i < 2; i++)
                #pragma unroll
                for (int j = 0; j < 4; j++) {
                    long idx = (long)(tm * 32 + ty * 2 + i) * Cc + tn * 64 + tx * 4 + j;
                    float xv = __ldcg(&X[idx]);
                    __stcg(&Xnb[idx], 1.5f * xv - 0.5f * ac2[i][j]);
                }
        }
        gridbar();
        float* tp = Xc; Xc = Xn; Xn = tp;
    }
}

// ================= tf32 mma primitives =================
__device__ __forceinline__ unsigned f2tf32(float f) {
    unsigned u; asm("cvt.rna.tf32.f32 %0, %1;" : "=r"(u) : "f"(f)); return u;
}
__device__ __forceinline__ void mma8(float* c, unsigned a0, unsigned a1, unsigned a2, unsigned a3,
                                     unsigned b0, unsigned b1) {
    asm volatile(
        "mma.sync.aligned.m16n8k8.row.col.f32.tf32.tf32.f32 "
        "{%0,%1,%2,%3}, {%4,%5,%6,%7}, {%8,%9}, {%0,%1,%2,%3};"
        : "+f"(c[0]), "+f"(c[1]), "+f"(c[2]), "+f"(c[3])
        : "r"(a0), "r"(a1), "r"(a2), "r"(a3), "r"(b0), "r"(b1));
}

// ================= tf32 tensor-core GEMM: BM=128 BN=128 BK=16, warp 64x32 =================
template<bool RELU, bool BIAS, bool RES>
__global__ __launch_bounds__(256, 2)
void gemm_tc(const float* __restrict__ A, const float* __restrict__ B,
             const float* __restrict__ bias, const float* __restrict__ Res,
             float* __restrict__ C,
             int Nstore, int K, int lda, int ldb, int Nreal, int Kb)
{
    __shared__ unsigned As[2][128][20];
    __shared__ unsigned Bsm[2][16][136];
    int tid = threadIdx.x;
    int lane = tid & 31, w = tid >> 5;
    int gr = lane >> 2, tg = lane & 3;
    int wm = w & 1, wn = w >> 1;          // warp tile rows wm*64, cols wn*32
    long m0 = (long)blockIdx.y * 128;
    int n0 = blockIdx.x * 128;

    int ar = tid >> 2, aq = tid & 3;      // A loader
    int bk = tid >> 4, bn = tid & 15;     // B loader

    float acc[4][4][4];
    #pragma unroll
    for (int i = 0; i < 4; i++)
        #pragma unroll
        for (int j = 0; j < 4; j++)
            #pragma unroll
            for (int e = 0; e < 4; e++) acc[i][j][e] = 0.f;

    int nk = K / 16;

    // prologue
    {
        #pragma unroll
        for (int h = 0; h < 2; h++) {
            int row = ar + h * 64;
            float4 v = *(const float4*)(A + (m0 + row) * lda + aq * 4);
            uint4 u = { f2tf32(v.x), f2tf32(v.y), f2tf32(v.z), f2tf32(v.w) };
            *(uint4*)&As[0][row][aq * 4] = u;
        }
        #pragma unroll
        for (int j = 0; j < 8; j++) {
            int n = bn + j * 16;
            int gn = n0 + n;
            float v = 0.f;
            if (bk < Kb && gn < Nreal) v = B[(long)bk * ldb + gn];
            Bsm[0][bk][n] = f2tf32(v);
        }
    }
    __syncthreads();

    for (int kt = 0; kt < nk; kt++) {
        int cur = kt & 1, nxt = cur ^ 1;
        bool more = (kt + 1 < nk);
        float4 ra[2];
        float rb[8];
        if (more) {
            int k0 = (kt + 1) * 16;
            #pragma unroll
            for (int h = 0; h < 2; h++) {
                int row = ar + h * 64;
                ra[h] = *(const float4*)(A + (m0 + row) * lda + k0 + aq * 4);
            }
            #pragma unroll
            for (int j = 0; j < 8; j++) {
                int n = bn + j * 16;
                int gk = k0 + bk, gn = n0 + n;
                rb[j] = (gk < Kb && gn < Nreal) ? B[(long)gk * ldb + gn] : 0.f;
            }
        }

        #pragma unroll
        for (int ks = 0; ks < 2; ks++) {
            int kb = ks * 8;
            unsigned bf[4][2];
            #pragma unroll
            for (int nt = 0; nt < 4; nt++) {
                int ncol = wn * 32 + nt * 8;
                bf[nt][0] = Bsm[cur][kb + tg    ][ncol + gr];
                bf[nt][1] = Bsm[cur][kb + tg + 4][ncol + gr];
            }
            #pragma unroll
            for (int mt = 0; mt < 4; mt++) {
                int mrow = wm * 64 + mt * 16;
                unsigned a0 = As[cur][mrow + gr    ][kb + tg    ];
                unsigned a1 = As[cur][mrow + gr + 8][kb + tg    ];
                unsigned a2 = As[cur][mrow + gr    ][kb + tg + 4];
                unsigned a3 = As[cur][mrow + gr + 8][kb + tg + 4];
                #pragma unroll
                for (int nt = 0; nt < 4; nt++)
                    mma8(acc[mt][nt], a0, a1, a2, a3, bf[nt][0], bf[nt][1]);
            }
        }

        if (more) {
            #pragma unroll
            for (int h = 0; h < 2; h++) {
                int row = ar + h * 64;
                uint4 u = { f2tf32(ra[h].x), f2tf32(ra[h].y), f2tf32(ra[h].z), f2tf32(ra[h].w) };
                *(uint4*)&As[nxt][row][aq * 4] = u;
            }
            #pragma unroll
            for (int j = 0; j < 8; j++) Bsm[nxt][bk][bn + j * 16] = f2tf32(rb[j]);
        }
        __syncthreads();
    }

    // epilogue
    #pragma unroll
    for (int mt = 0; mt < 4; mt++) {
        #pragma unroll
        for (int nt = 0; nt < 4; nt++) {
            int r0 = wm * 64 + mt * 16 + gr;
            int cb = n0 + wn * 32 + nt * 8 + 2 * tg;
            if (cb >= Nstore) continue;
            #pragma unroll
            for (int half = 0; half < 2; half++) {
                long gm = m0 + r0 + half * 8;
                float v0 = acc[mt][nt][half * 2 + 0];
                float v1 = acc[mt][nt][half * 2 + 1];
                if (BIAS) {
                    v0 += (cb     < Nreal) ? bias[cb]     : 0.f;
                    v1 += (cb + 1 < Nreal) ? bias[cb + 1] : 0.f;
                }
                if (RES) {
                    float2 rr = *(const float2*)(Res + gm * Nstore + cb);
                    v0 += rr.x; v1 += rr.y;
                }
                if (RELU) { v0 = fmaxf(v0, 0.f); v1 = fmaxf(v1, 0.f); }
                *(float2*)(C + gm * Nstore + cb) = make_float2(v0, v1);
            }
        }
    }
}

// ---------------- rmsnorm ----------------
__global__ __launch_bounds__(256)
void rmsnorm_k(const float* __restrict__ x, const float* __restrict__ scale,
               float* __restrict__ out)
{
    int warp = threadIdx.x >> 5, lane = threadIdx.x & 31;
    long t = (long)blockIdx.x * 8 + warp;
    const float* xr = x + t * Cc;
    float v[12], ss = 0.f;
    #pragma unroll
    for (int i = 0; i < 12; i++) { v[i] = xr[lane + i * 32]; ss += v[i] * v[i]; }
    #pragma unroll
    for (int o = 16; o > 0; o >>= 1) ss += __shfl_xor_sync(0xffffffffu, ss, o);
    float inv = rsqrtf(ss * (1.0f / Cc) + 1e-6f);
    float* orow = out + t * Cc;
    #pragma unroll
    for (int i = 0; i < 12; i++) orow[lane + i * 32] = v[i] * inv * scale[lane + i * 32];
}

// ---------------- pack ----------------
__global__ void pack_k(const float* __restrict__ Wq, const float* __restrict__ Wk,
                       const float* __restrict__ Wv, float* __restrict__ Wqkv)
{
    int i = blockIdx.x * 256 + threadIdx.x;
    if (i >= Hh * Cc * HSs) return;
    int h = i / (Cc * HSs);
    int rem = i % (Cc * HSs);
    int c = rem / HSs, d = rem % HSs;
    long row = (long)c * C3;
    Wqkv[row +           h * HSs + d] = Wq[i];
    Wqkv[row + Cc      + h * HSs + d] = Wk[i];
    Wqkv[row + 2 * Cc  + h * HSs + d] = Wv[i];
}

// ================= tensor-core causal flash attention (tf32) =================
// grid (4, 6, 256), 256 thr = 8 warps. S tile 64x64; warp w: rows (w&3)*16, cols (w>>2)*32.
__global__ __launch_bounds__(256, 2)
void flash_tc(const float* __restrict__ qkv, float* __restrict__ attn)
{
    extern __shared__ unsigned sm[];
    unsigned* Qs = sm;                       // [64][68]
    unsigned* Ks = Qs + 64 * FPQ;            // [64][68]
    unsigned* Ps = Ks + 64 * FPQ;            // [64][68]
    unsigned* Vs = Ps + 64 * FPQ;            // [64][72]
    float* redm = (float*)(Vs + 64 * FPV);   // [8][16]
    float* redl = redm + 8 * 16;             // [8][16]

    int qt = blockIdx.x, h = blockIdx.y, b = blockIdx.z;
    int tid = threadIdx.x;
    int lane = tid & 31, w = tid >> 5;
    int gr = lane >> 2, tg = lane & 3;
    int wr = (w & 3) * 16;
    int wc = (w >> 2) * 32;

    long base = (long)b * Tt * C3 + (long)h * HSs;

    // Q tile (scaled) -> smem tf32
    for (int f = tid; f < 64 * 16; f += 256) {
        int row = f >> 4, d4 = f & 15;
        float4 v = *(const float4*)(qkv + base + (long)(qt * 64 + row) * C3 + d4 * 4);
        uint4 u = { f2tf32(v.x * 0.125f), f2tf32(v.y * 0.125f),
                    f2tf32(v.z * 0.125f), f2tf32(v.w * 0.125f) };
        *(uint4*)&Qs[row * FPQ + d4 * 4] = u;
    }
    __syncthreads();

    unsigned qa[8][4];
    #pragma unroll
    for (int ks = 0; ks < 8; ks++) {
        qa[ks][0] = Qs[(wr + gr    ) * FPQ + ks * 8 + tg    ];
        qa[ks][1] = Qs[(wr + gr + 8) * FPQ + ks * 8 + tg    ];
        qa[ks][2] = Qs[(wr + gr    ) * FPQ + ks * 8 + tg + 4];
        qa[ks][3] = Qs[(wr + gr + 8) * FPQ + ks * 8 + tg + 4];
    }

    float oacc[4][4];
    #pragma unroll
    for (int i = 0; i < 4; i++)
        #pragma unroll
        for (int j = 0; j < 4; j++) oacc[i][j] = 0.f;
    float m0 = -1e30f, m1 = -1e30f, l0 = 0.f, l1 = 0.f;

    for (int kt = 0; kt <= qt; kt++) {
        __syncthreads();   // previous PV reads of Ps/Vs done; Ks free
        for (int f = tid; f < 64 * 16; f += 256) {
            int row = f >> 4, d4 = f & 15;
            long off = base + (long)(kt * 64 + row) * C3 + d4 * 4;
            float4 kv = *(const float4*)(qkv + off + Cc);
            float4 vv = *(const float4*)(qkv + off + 2 * Cc);
            uint4 ku = { f2tf32(kv.x), f2tf32(kv.y), f2tf32(kv.z), f2tf32(kv.w) };
            uint4 vu = { f2tf32(vv.x), f2tf32(vv.y), f2tf32(vv.z), f2tf32(vv.w) };
            *(uint4*)&Ks[row * FPQ + d4 * 4] = ku;
            *(uint4*)&Vs[row * FPV + d4 * 4] = vu;
        }
        __syncthreads();

        // S = Q @ K^T
        float sacc[4][4];
        #pragma unroll
        for (int i = 0; i < 4; i++)
            #pragma unroll
            for (int j = 0; j < 4; j++) sacc[i][j] = 0.f;
        #pragma unroll
        for (int ks = 0; ks < 8; ks++) {
            unsigned bf[4][2];
            #pragma unroll
            for (int nt = 0; nt < 4; nt++) {
                bf[nt][0] = Ks[(wc + nt * 8 + gr) * FPQ + ks * 8 + tg    ];
                bf[nt][1] = Ks[(wc + nt * 8 + gr) * FPQ + ks * 8 + tg + 4];
            }
            #pragma unroll
            for (int nt = 0; nt < 4; nt++)
                mma8(sacc[nt], qa[ks][0], qa[ks][1], qa[ks][2], qa[ks][3],
                     bf[nt][0], bf[nt][1]);
        }

        if (kt == qt) {
            #pragma unroll
            for (int nt = 0; nt < 4; nt++) {
                int c = wc + nt * 8 + 2 * tg;
                int r0 = wr + gr, r1 = r0 + 8;
                if (c     > r0) sacc[nt][0] = -1e30f;
                if (c + 1 > r0) sacc[nt][1] = -1e30f;
                if (c     > r1) sacc[nt][2] = -1e30f;
                if (c + 1 > r1) sacc[nt][3] = -1e30f;
            }
        }

        // row maxes (32-col warp chunk, then partner warp)
        float mx0 = -1e30f, mx1 = -1e30f;
        #pragma unroll
        for (int nt = 0; nt < 4; nt++) {
            mx0 = fmaxf(mx0, fmaxf(sacc[nt][0], sacc[nt][1]));
            mx1 = fmaxf(mx1, fmaxf(sacc[nt][2], sacc[nt][3]));
        }
        mx0 = fmaxf(mx0, __shfl_xor_sync(0xffffffffu, mx0, 1));
        mx0 = fmaxf(mx0, __shfl_xor_sync(0xffffffffu, mx0, 2));
        mx1 = fmaxf(mx1, __shfl_xor_sync(0xffffffffu, mx1, 1));
        mx1 = fmaxf(mx1, __shfl_xor_sync(0xffffffffu, mx1, 2));
        if (tg == 0) { redm[w * 16 + gr] = mx0; redm[w * 16 + gr + 8] = mx1; }
        __syncthreads();
        mx0 = fmaxf(mx0, redm[(w ^ 4) * 16 + gr]);
        mx1 = fmaxf(mx1, redm[(w ^ 4) * 16 + gr + 8]);
        float mn0 = fmaxf(m0, mx0), mn1 = fmaxf(m1, mx1);
        float corr0 = __expf(m0 - mn0), corr1 = __expf(m1 - mn1);

        float rs0 = 0.f, rs1 = 0.f;
        float p[4][4];
        #pragma unroll
        for (int nt = 0; nt < 4; nt++) {
            p[nt][0] = __expf(sacc[nt][0] - mn0);
            p[nt][1] = __expf(sacc[nt][1] - mn0);
            p[nt][2] = __expf(sacc[nt][2] - mn1);
            p[nt][3] = __expf(sacc[nt][3] - mn1);
            rs0 += p[nt][0] + p[nt][1];
            rs1 += p[nt][2] + p[nt][3];
        }
        rs0 += __shfl_xor_sync(0xffffffffu, rs0, 1);
        rs0 += __shfl_xor_sync(0xffffffffu, rs0, 2);
        rs1 += __shfl_xor_sync(0xffffffffu, rs1, 1);
        rs1 += __shfl_xor_sync(0xffffffffu, rs1, 2);
        if (tg == 0) { redl[w * 16 + gr] = rs0; redl[w * 16 + gr + 8] = rs1; }

        // store P as tf32
        #pragma unroll
        for (int nt = 0; nt < 4; nt++) {
            uint2 u0 = { f2tf32(p[nt][0]), f2tf32(p[nt][1]) };
            uint2 u1 = { f2tf32(p[nt][2]), f2tf32(p[nt][3]) };
            *(uint2*)&Ps[(wr + gr    ) * FPQ + wc + nt * 8 + 2 * tg] = u0;
            *(uint2*)&Ps[(wr + gr + 8) * FPQ + wc + nt * 8 + 2 * tg] = u1;
        }
        __syncthreads();
        l0 = l0 * corr0 + rs0 + redl[(w ^ 4) * 16 + gr];
        l1 = l1 * corr1 + rs1 + redl[(w ^ 4) * 16 + gr + 8];
        m0 = mn0; m1 = mn1;
        #pragma unroll
        for (int nt = 0; nt < 4; nt++) {
            oacc[nt][0] *= corr0; oacc[nt][1] *= corr0;
            oacc[nt][2] *= corr1; oacc[nt][3] *= corr1;
        }

        // O += P @ V
        #pragma unroll
        for (int ks = 0; ks < 8; ks++) {
            unsigned pa0 = Ps[(wr + gr    ) * FPQ + ks * 8 + tg    ];
            unsigned pa1 = Ps[(wr + gr + 8) * FPQ + ks * 8 + tg    ];
            unsigned pa2 = Ps[(wr + gr    ) * FPQ + ks * 8 + tg + 4];
            unsigned pa3 = Ps[(wr + gr + 8) * FPQ + ks * 8 + tg + 4];
            unsigned bf[4][2];
            #pragma unroll
            for (int nt = 0; nt < 4; nt++) {
                bf[nt][0] = Vs[(ks * 8 + tg    ) * FPV + wc + nt * 8 + gr];
                bf[nt][1] = Vs[(ks * 8 + tg + 4) * FPV + wc + nt * 8 + gr];
            }
            #pragma unroll
            for (int nt = 0; nt < 4; nt++)
                mma8(oacc[nt], pa0, pa1, pa2, pa3, bf[nt][0], bf[nt][1]);
        }
    }

    float i0 = 1.f / l0, i1 = 1.f / l1;
    long orow0 = ((long)b * Tt + qt * 64 + wr + gr) * Cc + h * HSs;
    long orow1 = orow0 + 8L * Cc;
    #pragma unroll
    for (int nt = 0; nt < 4; nt++) {
        int c = wc + nt * 8 + 2 * tg;
        *(float2*)(attn + orow0 + c) = make_float2(oacc[nt][0] * i0, oacc[nt][1] * i0);
        *(float2*)(attn + orow1 + c) = make_float2(oacc[nt][2] * i1, oacc[nt][3] * i1);
    }
}

// ---------------- host side ----------------
static float* symaddr(const void* sym) {
    void* p = nullptr;
    cudaGetSymbolAddress(&p, sym);
    return (float*)p;
}

#define FLASH_SMEM ((3 * 64 * FPQ + 64 * FPV) * 4 + 2 * 8 * 16 * 4)

extern "C" void kernel_launch(void* const* d_in, const int* in_sizes, int n_in,
                              void* d_out, int out_size)
{
    const float* x      = (const float*)d_in[0];
    const float* Wq     = (const float*)d_in[1];
    const float* Wk     = (const float*)d_in[2];
    const float* Wv     = (const float*)d_in[3];
    const float* Wp     = (const float*)d_in[4];
    const float* bp     = (const float*)d_in[5];
    const float* scale1 = (const float*)d_in[6];
    const float* scale2 = (const float*)d_in[7];
    const float* W1     = (const float*)d_in[8];
    const float* b1     = (const float*)d_in[9];
    const float* W2     = (const float*)d_in[10];
    const float* b2     = (const float*)d_in[11];
    const float* Wo_in  = (const float*)d_in[12];
    const float* Wo_out = (const float*)d_in[13];
    float* out = (float*)d_out;

    float* h1   = symaddr(g_h1);
    float* qkv  = symaddr(g_qkv);
    float* attn = symaddr(g_attn);
    float* h2   = symaddr(g_h2);
    float* h3   = symaddr(g_h3);
    float* h4   = symaddr(g_h4);
    float* ff   = symaddr(g_ff);
    float* h6   = symaddr(g_h6);
    float* X0   = symaddr(g_X0);
    float* Wqkv = symaddr(g_Wqkv);

    cudaFuncSetAttribute(flash_tc, cudaFuncAttributeMaxDynamicSharedMemorySize, FLASH_SMEM);

    // ---- orth via persistent Newton-Schulz ----
    ns_k<<<NS_CTAS, 256>>>(Wo_in, Wo_out);
    const float* O_in  = X0;
    const float* O_out = X0 + MSZ;

    // ---- pack + ln1 ----
    pack_k<<<(Hh * Cc * HSs + 255) / 256, 256>>>(Wq, Wk, Wv, Wqkv);
    rmsnorm_k<<<BT / 8, 256>>>(x, scale1, h1);

    // ---- qkv = h1 @ Wqkv ----
    gemm_tc<false, false, false><<<dim3(C3 / 128, BT / 128), 256>>>(
        h1, Wqkv, nullptr, nullptr, qkv, C3, Cc, Cc, C3, C3, Cc);

    // ---- attention ----
    flash_tc<<<dim3(Tt / 64, Hh, Bb), 256, FLASH_SMEM>>>(qkv, attn);

    // ---- h2 = attn @ Wp + bp + h1 ----
    gemm_tc<false, true, true><<<dim3(Cc / 128, BT / 128), 256>>>(
        attn, Wp, bp, h1, h2, Cc, Cc, Cc, Cc, Cc, Cc);

    // ---- ln2 ----
    rmsnorm_k<<<BT / 8, 256>>>(h2, scale2, h3);

    // ---- h4 = h3 @ O_in ----
    gemm_tc<false, false, false><<<dim3(Cc / 128, BT / 128), 256>>>(
        h3, O_in, nullptr, nullptr, h4, Cc, Cc, Cc, Cc, Cc, Cc);

    // ---- ff = relu(h4 @ W1 + b1), padded to 320 cols ----
    gemm_tc<true, true, false><<<dim3((PPAD + 127) / 128, BT / 128), 256>>>(
        h4, W1, b1, nullptr, ff, PPAD, Cc, Cc, Pp, Pp, Cc);

    // ---- h6 = ff @ W2 + b2 ----
    gemm_tc<false, true, false><<<dim3(Cc / 128, BT / 128), 256>>>(
        ff, W2, b2, nullptr, h6, Cc, PPAD, PPAD, Cc, Cc, Pp);

    // ---- out = h6 @ O_out + h6 ----
    gemm_tc<false, false, true><<<dim3(Cc / 128, BT / 128), 256>>>(
        h6, O_out, nullptr, h6, out, Cc, Cc, Cc, Cc, Cc, Cc);

    (void)in_sizes; (void)n_in; (void)out_size;
}